// round 3
// baseline (speedup 1.0000x reference)
#include <cuda_runtime.h>

#define DEV_INLINE __device__ __forceinline__

// fully-inline erf (Abramowitz-Stegun 7.1.26, |err| <= 1.5e-7) -> exact-gelu
static DEV_INLINE float erf_inline(float x){
    float ax = fabsf(x);
    float t = __frcp_rn(fmaf(0.3275911f, ax, 1.0f));
    float y = fmaf(t, 1.061405429f, -1.453152027f);
    y = fmaf(t, y, 1.421413741f);
    y = fmaf(t, y, -0.284496736f);
    y = fmaf(t, y, 0.254829592f);
    y = y * t;
    float e = __expf(-ax*ax);
    float r = fmaf(-y, e, 1.0f);
    return copysignf(r, x);
}
static DEV_INLINE float gelu_f(float x){
    return 0.5f * x * (1.f + erf_inline(x * 0.70710678118654752440f));
}
static DEV_INLINE float exp_inline(float x){ return __expf(x); }

#define NB 512
#define NO 181
#define NI 96
#define ND 16
#define BOI (NO*NI)   // 17376

// ---------------- scratch (device globals; referenced ONLY from device code) ----------------
__device__ float g_h1[NB*64*49];
__device__ float g_h2[NB*128*36];
__device__ float g_h3[NB*256*25];
__device__ float g_u [NB*NI*ND];
__device__ float g_uhat[(size_t)NB*NO*NI*ND];   // 569 MB
__device__ float g_bmat[NB*BOI];
__device__ float g_cmat[NB*BOI];
__device__ float g_x  [NB*NO*ND];
__device__ int   g_idx[NB*4];
__device__ float g_a1[2048*1024];
__device__ float g_a2[2048*768];
__device__ float g_a3[2048*512];
__device__ float g_a4[2048*512];
__device__ float g_a5[2048*256];

// ---------------- conv1: [512,3,8,8] -> gelu -> [512,64,7,7] ----------------
__global__ void __launch_bounds__(256) k_conv1(const float* __restrict__ x,
                                               const float* __restrict__ w,
                                               const float* __restrict__ bias){
    int idx = blockIdx.x*256 + threadIdx.x;
    if (idx >= NB*64*49) return;
    int p = idx % 49; int oc = (idx/49) & 63; int b = idx/(49*64);
    int y = p/7, xx = p%7;
    float acc = bias[oc];
    #pragma unroll
    for (int ci=0; ci<3; ci++){
        const float* xp = x + (b*3+ci)*64 + y*8 + xx;
        const float* wp = w + (oc*3+ci)*4;
        acc += xp[0]*wp[0] + xp[1]*wp[1] + xp[8]*wp[2] + xp[9]*wp[3];
    }
    g_h1[idx] = gelu_f(acc);
}

// ---------------- conv2: [512,64,7,7] -> gelu -> [512,128,6,6] ----------------
__global__ void __launch_bounds__(128) k_conv2(const float* __restrict__ w,
                                               const float* __restrict__ bias){
    __shared__ float sin_[64*49];
    int b = blockIdx.x; int tid = threadIdx.x; // 128
    for (int t=tid; t<64*49; t+=128) sin_[t] = g_h1[b*64*49 + t];
    __syncthreads();
    int oc = tid;
    float acc[36];
    #pragma unroll
    for (int p=0;p<36;p++) acc[p]=0.f;
    for (int ic=0; ic<64; ic++){
        const float* sp = &sin_[ic*49];
        const float* wp = w + (oc*64+ic)*4;
        float w00=wp[0], w01=wp[1], w10=wp[2], w11=wp[3];
        #pragma unroll
        for (int y=0;y<6;y++)
            #pragma unroll
            for (int xx=0;xx<6;xx++)
                acc[y*6+xx] += sp[y*7+xx]*w00 + sp[y*7+xx+1]*w01
                             + sp[(y+1)*7+xx]*w10 + sp[(y+1)*7+xx+1]*w11;
    }
    float bo = bias[oc];
    #pragma unroll
    for (int p=0;p<36;p++) g_h2[(b*128+oc)*36+p] = gelu_f(acc[p]+bo);
}

// ---------------- conv3: [512,128,6,6] -> gelu -> [512,256,5,5] ----------------
__global__ void __launch_bounds__(256) k_conv3(const float* __restrict__ w,
                                               const float* __restrict__ bias){
    __shared__ float sin_[128*36];
    int b = blockIdx.x; int tid = threadIdx.x; // 256
    for (int t=tid; t<128*36; t+=256) sin_[t]=g_h2[b*128*36+t];
    __syncthreads();
    int oc = tid;
    float a0[25];
    #pragma unroll
    for (int p=0;p<25;p++) a0[p]=0.f;
    for (int ic=0; ic<128; ic++){
        const float* sp = &sin_[ic*36];
        const float* wA = w + (oc*128+ic)*4;
        float A00=wA[0],A01=wA[1],A10=wA[2],A11=wA[3];
        #pragma unroll
        for (int y=0;y<5;y++)
            #pragma unroll
            for (int xx=0;xx<5;xx++){
                int p=y*5+xx, q=y*6+xx;
                a0[p] += sp[q]*A00 + sp[q+1]*A01 + sp[q+6]*A10 + sp[q+7]*A11;
            }
    }
    float bo0 = bias[oc];
    #pragma unroll
    for (int p=0;p<25;p++) g_h3[(b*256+oc)*25+p] = gelu_f(a0[p]+bo0);
}

// ---------------- primary caps conv + squash: -> u [512,96,16] ----------------
__global__ void __launch_bounds__(96) k_pc(const float* __restrict__ w,
                                           const float* __restrict__ bias){
    __shared__ float sin_[256*25];
    int b = blockIdx.x; int tid = threadIdx.x; // 96
    for (int t=tid; t<256*25; t+=96) sin_[t]=g_h3[b*256*25+t];
    __syncthreads();
    int oc = tid;
    float acc[16];
    #pragma unroll
    for (int p=0;p<16;p++) acc[p]=0.f;
    for (int ic=0; ic<256; ic++){
        const float* sp = &sin_[ic*25];
        const float* wp = w + (oc*256+ic)*4;
        float w00=wp[0], w01=wp[1], w10=wp[2], w11=wp[3];
        #pragma unroll
        for (int y=0;y<4;y++)
            #pragma unroll
            for (int xx=0;xx<4;xx++){
                int p=y*4+xx, q=y*5+xx;
                acc[p] += sp[q]*w00 + sp[q+1]*w01 + sp[q+5]*w10 + sp[q+6]*w11;
            }
    }
    float bo = bias[oc];
    float nn = 0.f;
    #pragma unroll
    for (int p=0;p<16;p++){ acc[p]+=bo; nn += acc[p]*acc[p]; }
    float n = __fsqrt_rn(nn);
    float sc = (1.f - exp_inline(-n)) * __frcp_rn(n + 1e-8f);
    #pragma unroll
    for (int p=0;p<16;p++) g_u[(b*NI+oc)*ND+p] = acc[p]*sc;
}

// ---------------- einsum: u_hat[b,o,i,d] = sum_k W[o,i,d,k] u[b,i,k] ----------------
__global__ void __launch_bounds__(384) k_einsum(const float* __restrict__ W){
    extern __shared__ float ush[];  // [16][96][20] padded
    int b0 = blockIdx.x * 16;
    int o  = blockIdx.y;
    int tid = threadIdx.x;
    for (int e=tid; e<16*NI*ND; e+=384){
        int bb = e/1536; int r = e - bb*1536; int i = r>>4; int k = r&15;
        ush[(bb*NI+i)*20 + k] = g_u[(b0+bb)*1536 + r];
    }
    __syncthreads();
    int i = tid>>2, dq = tid&3;
    const float4* Wv = (const float4*)(W + ((size_t)(o*NI + i)*ND + dq*4)*ND);
    float4 wr[16];
    #pragma unroll
    for (int t=0;t<16;t++) wr[t]=Wv[t];
    #pragma unroll 4
    for (int bb=0; bb<16; bb++){
        const float* ub = &ush[(bb*NI+i)*20];
        float4 u0=*(const float4*)(ub), u1=*(const float4*)(ub+4),
               u2=*(const float4*)(ub+8), u3=*(const float4*)(ub+12);
        float a0, a1, a2, a3;
        {
            float4 wa=wr[0], wb=wr[1], wc=wr[2], wd=wr[3];
            a0 = wa.x*u0.x + wa.y*u0.y + wa.z*u0.z + wa.w*u0.w
               + wb.x*u1.x + wb.y*u1.y + wb.z*u1.z + wb.w*u1.w
               + wc.x*u2.x + wc.y*u2.y + wc.z*u2.z + wc.w*u2.w
               + wd.x*u3.x + wd.y*u3.y + wd.z*u3.z + wd.w*u3.w;
        }
        {
            float4 wa=wr[4], wb=wr[5], wc=wr[6], wd=wr[7];
            a1 = wa.x*u0.x + wa.y*u0.y + wa.z*u0.z + wa.w*u0.w
               + wb.x*u1.x + wb.y*u1.y + wb.z*u1.z + wb.w*u1.w
               + wc.x*u2.x + wc.y*u2.y + wc.z*u2.z + wc.w*u2.w
               + wd.x*u3.x + wd.y*u3.y + wd.z*u3.z + wd.w*u3.w;
        }
        {
            float4 wa=wr[8], wb=wr[9], wc=wr[10], wd=wr[11];
            a2 = wa.x*u0.x + wa.y*u0.y + wa.z*u0.z + wa.w*u0.w
               + wb.x*u1.x + wb.y*u1.y + wb.z*u1.z + wb.w*u1.w
               + wc.x*u2.x + wc.y*u2.y + wc.z*u2.z + wc.w*u2.w
               + wd.x*u3.x + wd.y*u3.y + wd.z*u3.z + wd.w*u3.w;
        }
        {
            float4 wa=wr[12], wb=wr[13], wc=wr[14], wd=wr[15];
            a3 = wa.x*u0.x + wa.y*u0.y + wa.z*u0.z + wa.w*u0.w
               + wb.x*u1.x + wb.y*u1.y + wb.z*u1.z + wb.w*u1.w
               + wc.x*u2.x + wc.y*u2.y + wc.z*u2.z + wc.w*u2.w
               + wd.x*u3.x + wd.y*u3.y + wd.z*u3.z + wd.w*u3.w;
        }
        float4 outv = make_float4(a0,a1,a2,a3);
        *(float4*)&g_uhat[(((size_t)(b0+bb)*NO + o)*NI + i)*ND + dq*4] = outv;
    }
}

// ---------------- routing ----------------
__global__ void __launch_bounds__(256) k_binit(const float* __restrict__ caps_b){
    int t = blockIdx.x*256 + threadIdx.x;
    if (t < NB*BOI) g_bmat[t] = caps_b[t % BOI];
}

// softmax over o (axis 1) of g_bmat -> g_cmat ; thread per (b,i)
__global__ void __launch_bounds__(256) k_softmax(){
    int t = blockIdx.x*256 + threadIdx.x;
    if (t >= NB*NI) return;
    int b = t/NI, i = t - (t/NI)*NI;
    const float* p = g_bmat + b*BOI + i;
    float mx = -1e30f;
    for (int o=0;o<NO;o++) mx = fmaxf(mx, p[o*NI]);
    float sum = 0.f;
    for (int o=0;o<NO;o++) sum += exp_inline(p[o*NI]-mx);
    float inv = __frcp_rn(sum);
    float* cp = g_cmat + b*BOI + i;
    for (int o=0;o<NO;o++) cp[o*NI] = exp_inline(p[o*NI]-mx)*inv;
}

// one routing step; block per (o,b), 96 threads (thread = in-cap i)
__global__ void __launch_bounds__(96) k_route(int last){
    int o = blockIdx.x, b = blockIdx.y;
    int i = threadIdx.x;
    __shared__ float part[3][16];
    __shared__ float vsh[16];
    const float4* hp = (const float4*)&g_uhat[(((size_t)b*NO+o)*NI + i)*ND];
    float4 h0=hp[0], h1=hp[1], h2=hp[2], h3=hp[3];
    float ci = g_cmat[b*BOI + o*NI + i];
    float wv[16] = { ci*h0.x, ci*h0.y, ci*h0.z, ci*h0.w,
                     ci*h1.x, ci*h1.y, ci*h1.z, ci*h1.w,
                     ci*h2.x, ci*h2.y, ci*h2.z, ci*h2.w,
                     ci*h3.x, ci*h3.y, ci*h3.z, ci*h3.w };
    #pragma unroll
    for (int off=16; off>0; off>>=1){
        #pragma unroll
        for (int d=0; d<16; d++) wv[d] += __shfl_down_sync(0xffffffffu, wv[d], off);
    }
    int warp = i>>5, lane = i&31;
    if (lane==0){
        #pragma unroll
        for (int d=0; d<16; d++) part[warp][d]=wv[d];
    }
    __syncthreads();
    if (i<16){
        float s = part[0][i]+part[1][i]+part[2][i];
        float nn = s*s;
        #pragma unroll
        for (int off=8; off>0; off>>=1) nn += __shfl_xor_sync(0x0000ffffu, nn, off);
        float n = __fsqrt_rn(nn);
        float sc = (1.f - exp_inline(-n)) * __frcp_rn(n + 1e-8f);
        float vd = s*sc;
        vsh[i]=vd;
        if (last) g_x[(b*NO+o)*ND + i] = vd;
    }
    __syncthreads();
    if (!last){
        float dot = vsh[0]*h0.x + vsh[1]*h0.y + vsh[2]*h0.z + vsh[3]*h0.w
                  + vsh[4]*h1.x + vsh[5]*h1.y + vsh[6]*h1.z + vsh[7]*h1.w
                  + vsh[8]*h2.x + vsh[9]*h2.y + vsh[10]*h2.z + vsh[11]*h2.w
                  + vsh[12]*h3.x + vsh[13]*h3.y + vsh[14]*h3.z + vsh[15]*h3.w;
        g_bmat[b*BOI + o*NI + i] += dot;
    }
}

// ---------------- length, normalize, peak-pick top4 ----------------
__global__ void __launch_bounds__(192) k_peaks(float* __restrict__ d_out){
    __shared__ float len[192];
    __shared__ float pk[192];
    __shared__ float s_sum;
    int b = blockIdx.x, t = threadIdx.x; // 192
    float n = 0.f;
    if (t < NO){
        const float4* xp = (const float4*)&g_x[(b*NO+t)*ND];
        float4 a=xp[0], b4=xp[1], c=xp[2], d=xp[3];
        float nn = a.x*a.x+a.y*a.y+a.z*a.z+a.w*a.w
                 + b4.x*b4.x+b4.y*b4.y+b4.z*b4.z+b4.w*b4.w
                 + c.x*c.x+c.y*c.y+c.z*c.z+c.w*c.w
                 + d.x*d.x+d.y*d.y+d.z*d.z+d.w*d.w;
        n = __fsqrt_rn(nn);
    }
    len[t] = (t < NO) ? n : 0.f;
    __syncthreads();
    if (t==0){
        float s=0.f;
        for (int o=0;o<NO;o++) s+=len[o];
        s_sum = s + 1e-8f;
    }
    __syncthreads();
    if (t < NO) len[t] = len[t]/s_sum;
    __syncthreads();
    if (t < NO){
        float m = -1e30f;
        #pragma unroll
        for (int dd=-5; dd<=5; dd++){
            int oo = t+dd;
            if (oo>=0 && oo<NO) m = fmaxf(m, len[oo]);
        }
        pk[t] = (len[t]==m) ? len[t] : 0.f;
        d_out[NB*128*4 + b*NO + t] = len[t];
    }
    __syncthreads();
    if (t==0){
        int i0, i1, i2, i3;
        {
            float bv=-1.f; int bi=0;
            for (int o=0;o<NO;o++){ float v=pk[o]; if (v>bv){ bv=v; bi=o; } }
            i0=bi; pk[bi]=-2.f;
        }
        {
            float bv=-1.f; int bi=0;
            for (int o=0;o<NO;o++){ float v=pk[o]; if (v>bv){ bv=v; bi=o; } }
            i1=bi; pk[bi]=-2.f;
        }
        {
            float bv=-1.f; int bi=0;
            for (int o=0;o<NO;o++){ float v=pk[o]; if (v>bv){ bv=v; bi=o; } }
            i2=bi; pk[bi]=-2.f;
        }
        {
            float bv=-1.f; int bi=0;
            for (int o=0;o<NO;o++){ float v=pk[o]; if (v>bv){ bv=v; bi=o; } }
            i3=bi;
        }
        int tmp;
        if (i0>i1){tmp=i0;i0=i1;i1=tmp;}
        if (i2>i3){tmp=i2;i2=i3;i3=tmp;}
        if (i0>i2){tmp=i0;i0=i2;i2=tmp;}
        if (i1>i3){tmp=i1;i1=i3;i3=tmp;}
        if (i1>i2){tmp=i1;i1=i2;i2=tmp;}
        g_idx[b*4+0]=i0; g_idx[b*4+1]=i1; g_idx[b*4+2]=i2; g_idx[b*4+3]=i3;
    }
}

// ---------------- fc1 (sparse gather GEMV) -> gelu -> g_a1 [2048,1024] ----------------
__global__ void __launch_bounds__(256) k_fc1(const float* __restrict__ w,
                                             const float* __restrict__ bias){
    int j = blockIdx.x*256 + threadIdx.x;
    int row = blockIdx.y;              // 0..2047 = b*4 + k
    if (j >= 1024) return;
    int b = row>>2, k = row&3;
    int id = g_idx[b*4+k];
    const float* xv = &g_x[(b*NO+id)*ND];
    float acc = bias[j];
    #pragma unroll
    for (int d=0; d<16; d++) acc += xv[d]*w[(id*16+d)*1024 + j];
    g_a1[row*1024 + j] = gelu_f(acc);
}

// ---------------- generic tiled fp32 GEMM over scratch buffers ----------------
// sel picks (A, C) from device globals; HEAD writes transposed to d_out.
template<int GELU, int HEAD>
__global__ void __launch_bounds__(256) k_gemm(const float* __restrict__ W,
                                              const float* __restrict__ bias,
                                              float* __restrict__ Cout,
                                              int K, int N, int sel){
    const float* A; float* C;
    switch (sel){
        case 0: A = g_a1; C = g_a2; break;
        case 1: A = g_a2; C = g_a3; break;
        case 2: A = g_a3; C = g_a4; break;
        case 3: A = g_a4; C = g_a5; break;
        default: A = g_a5; C = Cout; break;
    }
    __shared__ float As[16][64];
    __shared__ float Bs[16][64];
    int tid = threadIdx.x;
    int row0 = blockIdx.y*64, col0 = blockIdx.x*64;
    int tr = tid>>4, tc = tid&15;
    int lr = tid>>2,  lk4 = (tid&3)*4;
    int lkk = tid>>4, lc4 = (tid&15)*4;
    float acc[4][4];
    #pragma unroll
    for (int u=0;u<4;u++)
        #pragma unroll
        for (int v=0;v<4;v++) acc[u][v]=0.f;
    for (int k0=0; k0<K; k0+=16){
        float4 av = *(const float4*)&A[(size_t)(row0+lr)*K + k0 + lk4];
        As[lk4+0][lr]=av.x; As[lk4+1][lr]=av.y; As[lk4+2][lr]=av.z; As[lk4+3][lr]=av.w;
        float4 bv = *(const float4*)&W[(size_t)(k0+lkk)*N + col0 + lc4];
        *(float4*)&Bs[lkk][lc4] = bv;
        __syncthreads();
        #pragma unroll
        for (int kk=0; kk<16; kk++){
            float4 a4 = *(const float4*)&As[kk][tr*4];
            float4 b4 = *(const float4*)&Bs[kk][tc*4];
            acc[0][0] += a4.x*b4.x; acc[0][1] += a4.x*b4.y; acc[0][2] += a4.x*b4.z; acc[0][3] += a4.x*b4.w;
            acc[1][0] += a4.y*b4.x; acc[1][1] += a4.y*b4.y; acc[1][2] += a4.y*b4.z; acc[1][3] += a4.y*b4.w;
            acc[2][0] += a4.z*b4.x; acc[2][1] += a4.z*b4.y; acc[2][2] += a4.z*b4.z; acc[2][3] += a4.z*b4.w;
            acc[3][0] += a4.w*b4.x; acc[3][1] += a4.w*b4.y; acc[3][2] += a4.w*b4.z; acc[3][3] += a4.w*b4.w;
        }
        __syncthreads();
    }
    #pragma unroll
    for (int u=0;u<4;u++){
        int r = row0 + tr*4 + u;
        #pragma unroll
        for (int v=0;v<4;v++){
            int c = col0 + tc*4 + v;
            float val = acc[u][v] + bias[c];
            if (GELU) val = gelu_f(val);
            if (HEAD) C[(r>>2)*512 + c*4 + (r&3)] = val;  // out[b][a][k]
            else      C[(size_t)r*N + c] = val;
        }
    }
}

// ---------------- launch ----------------
extern "C" void kernel_launch(void* const* d_in, const int* in_sizes, int n_in,
                              void* d_out, int out_size){
    const float* scm     = (const float*)d_in[0];
    // d_in[1] = K (always 4 in this dataset)
    const float* w1 = (const float*)d_in[2];  const float* b1 = (const float*)d_in[3];
    const float* w2 = (const float*)d_in[4];  const float* b2 = (const float*)d_in[5];
    const float* w3 = (const float*)d_in[6];  const float* b3 = (const float*)d_in[7];
    const float* pw = (const float*)d_in[8];  const float* pb = (const float*)d_in[9];
    const float* capsW = (const float*)d_in[10];
    const float* capsB = (const float*)d_in[11];
    const float* f1w = (const float*)d_in[12]; const float* f1b = (const float*)d_in[13];
    const float* f2w = (const float*)d_in[14]; const float* f2b = (const float*)d_in[15];
    const float* f3w = (const float*)d_in[16]; const float* f3b = (const float*)d_in[17];
    const float* f4w = (const float*)d_in[18]; const float* f4b = (const float*)d_in[19];
    const float* f5w = (const float*)d_in[20]; const float* f5b = (const float*)d_in[21];
    const float* hw  = (const float*)d_in[22]; const float* hb  = (const float*)d_in[23];
    float* out = (float*)d_out;

    const int einsum_smem = 16*NI*20*4;  // 122880 B
    cudaFuncSetAttribute(k_einsum, cudaFuncAttributeMaxDynamicSharedMemorySize, einsum_smem);

    k_conv1<<<(NB*64*49 + 255)/256, 256>>>(scm, w1, b1);
    k_conv2<<<NB, 128>>>(w2, b2);
    k_conv3<<<NB, 256>>>(w3, b3);
    k_pc   <<<NB,  96>>>(pw, pb);

    k_einsum<<<dim3(32, NO), 384, einsum_smem>>>(capsW);

    k_binit<<<(NB*BOI + 255)/256, 256>>>(capsB);
    for (int r=0; r<3; r++){
        k_softmax<<<(NB*NI + 255)/256, 256>>>();
        k_route<<<dim3(NO, NB), 96>>>(r==2 ? 1 : 0);
    }

    k_peaks<<<NB, 192>>>(out);

    k_fc1<<<dim3(4, 2048), 256>>>(f1w, f1b);
    k_gemm<1,0><<<dim3(12, 32), 256>>>(f2w, f2b, nullptr, 1024, 768, 0);
    k_gemm<1,0><<<dim3(8,  32), 256>>>(f3w, f3b, nullptr, 768,  512, 1);
    k_gemm<1,0><<<dim3(8,  32), 256>>>(f4w, f4b, nullptr, 512,  512, 2);
    k_gemm<1,0><<<dim3(4,  32), 256>>>(f5w, f5b, nullptr, 512,  256, 3);
    k_gemm<0,1><<<dim3(2,  32), 256>>>(hw,  hb,  out,     256,  128, 4);
    (void)in_sizes; (void)n_in; (void)out_size;
}

// round 4
// speedup vs baseline: 1.0178x; 1.0178x over previous
#include <cuda_runtime.h>
#include <cuda_fp16.h>

#define DEV_INLINE __device__ __forceinline__

// fully-inline erf (Abramowitz-Stegun 7.1.26, |err| <= 1.5e-7) -> exact-gelu
static DEV_INLINE float erf_inline(float x){
    float ax = fabsf(x);
    float t = __frcp_rn(fmaf(0.3275911f, ax, 1.0f));
    float y = fmaf(t, 1.061405429f, -1.453152027f);
    y = fmaf(t, y, 1.421413741f);
    y = fmaf(t, y, -0.284496736f);
    y = fmaf(t, y, 0.254829592f);
    y = y * t;
    float e = __expf(-ax*ax);
    float r = fmaf(-y, e, 1.0f);
    return copysignf(r, x);
}
static DEV_INLINE float gelu_f(float x){
    return 0.5f * x * (1.f + erf_inline(x * 0.70710678118654752440f));
}
static DEV_INLINE float exp_inline(float x){ return __expf(x); }

#define NB 512
#define NO 181
#define NI 96
#define ND 16
#define BOI (NO*NI)   // 17376

// ---------------- scratch (device globals; referenced ONLY from device code) ----------------
__device__ float  g_h1[NB*64*49];
__device__ float  g_h2[NB*128*36];
__device__ float  g_h3[NB*256*25];
__device__ float  g_u [NB*NI*ND];
__device__ __half g_uhat[(size_t)NB*NO*NI*ND];   // 285 MB (fp16)
__device__ float  g_bmat[NB*BOI];
__device__ float  g_cmat[NB*BOI];
__device__ float  g_x  [NB*NO*ND];
__device__ int    g_idx[NB*4];
__device__ float  g_a1[2048*1024];
__device__ float  g_a2[2048*768];
__device__ float  g_a3[2048*512];
__device__ float  g_a4[2048*512];
__device__ float  g_a5[2048*256];

// ---------------- conv1: [512,3,8,8] -> gelu -> [512,64,7,7] ----------------
__global__ void __launch_bounds__(256) k_conv1(const float* __restrict__ x,
                                               const float* __restrict__ w,
                                               const float* __restrict__ bias){
    int idx = blockIdx.x*256 + threadIdx.x;
    if (idx >= NB*64*49) return;
    int p = idx % 49; int oc = (idx/49) & 63; int b = idx/(49*64);
    int y = p/7, xx = p%7;
    float acc = bias[oc];
    #pragma unroll
    for (int ci=0; ci<3; ci++){
        const float* xp = x + (b*3+ci)*64 + y*8 + xx;
        const float* wp = w + (oc*3+ci)*4;
        acc += xp[0]*wp[0] + xp[1]*wp[1] + xp[8]*wp[2] + xp[9]*wp[3];
    }
    g_h1[idx] = gelu_f(acc);
}

// ---------------- conv2: [512,64,7,7] -> gelu -> [512,128,6,6] ----------------
// 512 thr: (oc 0..127) x (quad 0..3); quad owns a 3x3 output region (4x4 input patch)
__global__ void __launch_bounds__(512) k_conv2(const float* __restrict__ w,
                                               const float* __restrict__ bias){
    __shared__ float sin_[64*49];
    int b = blockIdx.x; int tid = threadIdx.x;
    for (int t=tid; t<64*49; t+=512) sin_[t] = g_h1[b*64*49 + t];
    __syncthreads();
    int oc = tid>>2, quad = tid&3;
    int qy = quad>>1, qx = quad&1;
    int r0 = qy*3, c0 = qx*3;
    float acc[3][3];
    #pragma unroll
    for (int u=0;u<3;u++)
        #pragma unroll
        for (int v=0;v<3;v++) acc[u][v]=0.f;
    for (int ic=0; ic<64; ic++){
        const float* sp = &sin_[ic*49];
        float s[4][4];
        #pragma unroll
        for (int dy=0;dy<4;dy++)
            #pragma unroll
            for (int dx=0;dx<4;dx++) s[dy][dx] = sp[(r0+dy)*7 + (c0+dx)];
        const float* wp = w + (oc*64+ic)*4;
        float w00=wp[0], w01=wp[1], w10=wp[2], w11=wp[3];
        #pragma unroll
        for (int ry=0;ry<3;ry++)
            #pragma unroll
            for (int rx=0;rx<3;rx++)
                acc[ry][rx] += s[ry][rx]*w00 + s[ry][rx+1]*w01
                             + s[ry+1][rx]*w10 + s[ry+1][rx+1]*w11;
    }
    float bo = bias[oc];
    #pragma unroll
    for (int ry=0;ry<3;ry++)
        #pragma unroll
        for (int rx=0;rx<3;rx++)
            g_h2[(b*128+oc)*36 + (r0+ry)*6 + (c0+rx)] = gelu_f(acc[ry][rx]+bo);
}

// ---------------- conv3: [512,128,6,6] -> gelu -> [512,256,5,5] ----------------
// 1024 thr: (oc 0..255) x (quad 0..3); quad regions 3/2 rows x 3/2 cols; clamp reads.
__global__ void __launch_bounds__(1024) k_conv3(const float* __restrict__ w,
                                                const float* __restrict__ bias){
    __shared__ float sin_[128*36];
    int b = blockIdx.x; int tid = threadIdx.x;
    for (int t=tid; t<128*36; t+=1024) sin_[t]=g_h2[b*128*36+t];
    __syncthreads();
    int oc = tid>>2, quad = tid&3;
    int qy = quad>>1, qx = quad&1;
    int r0 = qy*3, c0 = qx*3;
    int rh = qy ? 2 : 3, rw = qx ? 2 : 3;
    float acc[3][3];
    #pragma unroll
    for (int u=0;u<3;u++)
        #pragma unroll
        for (int v=0;v<3;v++) acc[u][v]=0.f;
    for (int ic=0; ic<128; ic++){
        const float* sp = &sin_[ic*36];
        float s[4][4];
        #pragma unroll
        for (int dy=0;dy<4;dy++){
            int yy = r0+dy; if (yy>5) yy=5;
            #pragma unroll
            for (int dx=0;dx<4;dx++){
                int xx = c0+dx; if (xx>5) xx=5;
                s[dy][dx] = sp[yy*6+xx];
            }
        }
        const float* wp = w + (oc*128+ic)*4;
        float w00=wp[0], w01=wp[1], w10=wp[2], w11=wp[3];
        #pragma unroll
        for (int ry=0;ry<3;ry++)
            #pragma unroll
            for (int rx=0;rx<3;rx++)
                acc[ry][rx] += s[ry][rx]*w00 + s[ry][rx+1]*w01
                             + s[ry+1][rx]*w10 + s[ry+1][rx+1]*w11;
    }
    float bo = bias[oc];
    #pragma unroll
    for (int ry=0;ry<3;ry++)
        #pragma unroll
        for (int rx=0;rx<3;rx++)
            if (ry<rh && rx<rw)
                g_h3[(b*256+oc)*25 + (r0+ry)*5 + (c0+rx)] = gelu_f(acc[ry][rx]+bo);
}

// ---------------- primary caps conv + squash: -> u [512,96,16] ----------------
// 384 thr: (oc 0..95) x (quad 0..3); quad owns 2x2 output (3x3 input patch).
// squash norm reduced across the 4 lanes of an oc via shfl_xor (lanes are consecutive).
__global__ void __launch_bounds__(384) k_pc(const float* __restrict__ w,
                                            const float* __restrict__ bias){
    __shared__ float sin_[256*25];
    int b = blockIdx.x; int tid = threadIdx.x;
    for (int t=tid; t<256*25; t+=384) sin_[t]=g_h3[b*256*25+t];
    __syncthreads();
    int oc = tid>>2, quad = tid&3;
    int qy = quad>>1, qx = quad&1;
    int r0 = qy*2, c0 = qx*2;
    float acc[2][2];
    acc[0][0]=0.f; acc[0][1]=0.f; acc[1][0]=0.f; acc[1][1]=0.f;
    for (int ic=0; ic<256; ic++){
        const float* sp = &sin_[ic*25];
        float s[3][3];
        #pragma unroll
        for (int dy=0;dy<3;dy++)
            #pragma unroll
            for (int dx=0;dx<3;dx++) s[dy][dx] = sp[(r0+dy)*5 + (c0+dx)];
        const float* wp = w + (oc*256+ic)*4;
        float w00=wp[0], w01=wp[1], w10=wp[2], w11=wp[3];
        #pragma unroll
        for (int ry=0;ry<2;ry++)
            #pragma unroll
            for (int rx=0;rx<2;rx++)
                acc[ry][rx] += s[ry][rx]*w00 + s[ry][rx+1]*w01
                             + s[ry+1][rx]*w10 + s[ry+1][rx+1]*w11;
    }
    float bo = bias[oc];
    float nn = 0.f;
    #pragma unroll
    for (int ry=0;ry<2;ry++)
        #pragma unroll
        for (int rx=0;rx<2;rx++){ acc[ry][rx]+=bo; nn += acc[ry][rx]*acc[ry][rx]; }
    nn += __shfl_xor_sync(0xffffffffu, nn, 1);
    nn += __shfl_xor_sync(0xffffffffu, nn, 2);
    float n = __fsqrt_rn(nn);
    float sc = (1.f - exp_inline(-n)) * __frcp_rn(n + 1e-8f);
    #pragma unroll
    for (int ry=0;ry<2;ry++)
        #pragma unroll
        for (int rx=0;rx<2;rx++)
            g_u[(b*NI+oc)*ND + (r0+ry)*4 + (c0+rx)] = acc[ry][rx]*sc;
}

// ---------------- einsum: u_hat[b,o,i,d] = sum_k W[o,i,d,k] u[b,i,k] (fp16 out) ----------------
__global__ void __launch_bounds__(384) k_einsum(const float* __restrict__ W){
    extern __shared__ float ush[];  // [16][96][20] padded
    int b0 = blockIdx.x * 16;
    int o  = blockIdx.y;
    int tid = threadIdx.x;
    for (int e=tid; e<16*NI*ND; e+=384){
        int bb = e/1536; int r = e - bb*1536; int i = r>>4; int k = r&15;
        ush[(bb*NI+i)*20 + k] = g_u[(b0+bb)*1536 + r];
    }
    __syncthreads();
    int i = tid>>2, dq = tid&3;
    const float4* Wv = (const float4*)(W + ((size_t)(o*NI + i)*ND + dq*4)*ND);
    float4 wr[16];
    #pragma unroll
    for (int t=0;t<16;t++) wr[t]=Wv[t];
    #pragma unroll 4
    for (int bb=0; bb<16; bb++){
        const float* ub = &ush[(bb*NI+i)*20];
        float4 u0=*(const float4*)(ub), u1=*(const float4*)(ub+4),
               u2=*(const float4*)(ub+8), u3=*(const float4*)(ub+12);
        float a0, a1, a2, a3;
        {
            float4 wa=wr[0], wb=wr[1], wc=wr[2], wd=wr[3];
            a0 = wa.x*u0.x + wa.y*u0.y + wa.z*u0.z + wa.w*u0.w
               + wb.x*u1.x + wb.y*u1.y + wb.z*u1.z + wb.w*u1.w
               + wc.x*u2.x + wc.y*u2.y + wc.z*u2.z + wc.w*u2.w
               + wd.x*u3.x + wd.y*u3.y + wd.z*u3.z + wd.w*u3.w;
        }
        {
            float4 wa=wr[4], wb=wr[5], wc=wr[6], wd=wr[7];
            a1 = wa.x*u0.x + wa.y*u0.y + wa.z*u0.z + wa.w*u0.w
               + wb.x*u1.x + wb.y*u1.y + wb.z*u1.z + wb.w*u1.w
               + wc.x*u2.x + wc.y*u2.y + wc.z*u2.z + wc.w*u2.w
               + wd.x*u3.x + wd.y*u3.y + wd.z*u3.z + wd.w*u3.w;
        }
        {
            float4 wa=wr[8], wb=wr[9], wc=wr[10], wd=wr[11];
            a2 = wa.x*u0.x + wa.y*u0.y + wa.z*u0.z + wa.w*u0.w
               + wb.x*u1.x + wb.y*u1.y + wb.z*u1.z + wb.w*u1.w
               + wc.x*u2.x + wc.y*u2.y + wc.z*u2.z + wc.w*u2.w
               + wd.x*u3.x + wd.y*u3.y + wd.z*u3.z + wd.w*u3.w;
        }
        {
            float4 wa=wr[12], wb=wr[13], wc=wr[14], wd=wr[15];
            a3 = wa.x*u0.x + wa.y*u0.y + wa.z*u0.z + wa.w*u0.w
               + wb.x*u1.x + wb.y*u1.y + wb.z*u1.z + wb.w*u1.w
               + wc.x*u2.x + wc.y*u2.y + wc.z*u2.z + wc.w*u2.w
               + wd.x*u3.x + wd.y*u3.y + wd.z*u3.z + wd.w*u3.w;
        }
        __half2 p0 = __floats2half2_rn(a0, a1);
        __half2 p1 = __floats2half2_rn(a2, a3);
        size_t base = (((size_t)(b0+bb)*NO + o)*NI + i)*ND + dq*4;
        *(__half2*)&g_uhat[base]     = p0;
        *(__half2*)&g_uhat[base + 2] = p1;
    }
}

// ---------------- routing ----------------
__global__ void __launch_bounds__(256) k_binit(const float* __restrict__ caps_b){
    int t = blockIdx.x*256 + threadIdx.x;
    if (t < NB*BOI) g_bmat[t] = caps_b[t % BOI];
}

// softmax over o (axis 1) of g_bmat -> g_cmat ; thread per (b,i)
__global__ void __launch_bounds__(256) k_softmax(){
    int t = blockIdx.x*256 + threadIdx.x;
    if (t >= NB*NI) return;
    int b = t/NI, i = t - (t/NI)*NI;
    const float* p = g_bmat + b*BOI + i;
    float mx = -1e30f;
    for (int o=0;o<NO;o++) mx = fmaxf(mx, p[o*NI]);
    float sum = 0.f;
    for (int o=0;o<NO;o++) sum += exp_inline(p[o*NI]-mx);
    float inv = __frcp_rn(sum);
    float* cp = g_cmat + b*BOI + i;
    for (int o=0;o<NO;o++) cp[o*NI] = exp_inline(p[o*NI]-mx)*inv;
}

// one routing step; block per (o,b), 96 threads (thread = in-cap i); u_hat fp16
__global__ void __launch_bounds__(96) k_route(int last){
    int o = blockIdx.x, b = blockIdx.y;
    int i = threadIdx.x;
    __shared__ float part[3][16];
    __shared__ float vsh[16];
    size_t base = (((size_t)b*NO+o)*NI + i)*ND;
    float4 raw0 = *(const float4*)&g_uhat[base];      // 8 halves
    float4 raw1 = *(const float4*)&g_uhat[base + 8];  // 8 halves
    float h[16];
    {
        const __half2* q = (const __half2*)&raw0;
        #pragma unroll
        for (int t=0;t<4;t++){ float2 f = __half22float2(q[t]); h[t*2]=f.x; h[t*2+1]=f.y; }
        const __half2* q2 = (const __half2*)&raw1;
        #pragma unroll
        for (int t=0;t<4;t++){ float2 f = __half22float2(q2[t]); h[8+t*2]=f.x; h[8+t*2+1]=f.y; }
    }
    float ci = g_cmat[b*BOI + o*NI + i];
    float wv[16];
    #pragma unroll
    for (int d=0;d<16;d++) wv[d] = ci*h[d];
    #pragma unroll
    for (int off=16; off>0; off>>=1){
        #pragma unroll
        for (int d=0; d<16; d++) wv[d] += __shfl_down_sync(0xffffffffu, wv[d], off);
    }
    int warp = i>>5, lane = i&31;
    if (lane==0){
        #pragma unroll
        for (int d=0; d<16; d++) part[warp][d]=wv[d];
    }
    __syncthreads();
    if (i<16){
        float s = part[0][i]+part[1][i]+part[2][i];
        float nn = s*s;
        #pragma unroll
        for (int off=8; off>0; off>>=1) nn += __shfl_xor_sync(0x0000ffffu, nn, off);
        float n = __fsqrt_rn(nn);
        float sc = (1.f - exp_inline(-n)) * __frcp_rn(n + 1e-8f);
        float vd = s*sc;
        vsh[i]=vd;
        if (last) g_x[(b*NO+o)*ND + i] = vd;
    }
    __syncthreads();
    if (!last){
        float dot = 0.f;
        #pragma unroll
        for (int d=0;d<16;d++) dot += vsh[d]*h[d];
        g_bmat[b*BOI + o*NI + i] += dot;
    }
}

// ---------------- length, normalize, peak-pick top4 ----------------
__global__ void __launch_bounds__(192) k_peaks(float* __restrict__ d_out){
    __shared__ float len[192];
    __shared__ float pk[192];
    __shared__ float s_sum;
    int b = blockIdx.x, t = threadIdx.x; // 192
    float n = 0.f;
    if (t < NO){
        const float4* xp = (const float4*)&g_x[(b*NO+t)*ND];
        float4 a=xp[0], b4=xp[1], c=xp[2], d=xp[3];
        float nn = a.x*a.x+a.y*a.y+a.z*a.z+a.w*a.w
                 + b4.x*b4.x+b4.y*b4.y+b4.z*b4.z+b4.w*b4.w
                 + c.x*c.x+c.y*c.y+c.z*c.z+c.w*c.w
                 + d.x*d.x+d.y*d.y+d.z*d.z+d.w*d.w;
        n = __fsqrt_rn(nn);
    }
    len[t] = (t < NO) ? n : 0.f;
    __syncthreads();
    if (t==0){
        float s=0.f;
        for (int o=0;o<NO;o++) s+=len[o];
        s_sum = s + 1e-8f;
    }
    __syncthreads();
    if (t < NO) len[t] = len[t]/s_sum;
    __syncthreads();
    if (t < NO){
        float m = -1e30f;
        #pragma unroll
        for (int dd=-5; dd<=5; dd++){
            int oo = t+dd;
            if (oo>=0 && oo<NO) m = fmaxf(m, len[oo]);
        }
        pk[t] = (len[t]==m) ? len[t] : 0.f;
        d_out[NB*128*4 + b*NO + t] = len[t];
    }
    __syncthreads();
    if (t==0){
        int i0, i1, i2, i3;
        {
            float bv=-1.f; int bi=0;
            for (int o=0;o<NO;o++){ float v=pk[o]; if (v>bv){ bv=v; bi=o; } }
            i0=bi; pk[bi]=-2.f;
        }
        {
            float bv=-1.f; int bi=0;
            for (int o=0;o<NO;o++){ float v=pk[o]; if (v>bv){ bv=v; bi=o; } }
            i1=bi; pk[bi]=-2.f;
        }
        {
            float bv=-1.f; int bi=0;
            for (int o=0;o<NO;o++){ float v=pk[o]; if (v>bv){ bv=v; bi=o; } }
            i2=bi; pk[bi]=-2.f;
        }
        {
            float bv=-1.f; int bi=0;
            for (int o=0;o<NO;o++){ float v=pk[o]; if (v>bv){ bv=v; bi=o; } }
            i3=bi;
        }
        int tmp;
        if (i0>i1){tmp=i0;i0=i1;i1=tmp;}
        if (i2>i3){tmp=i2;i2=i3;i3=tmp;}
        if (i0>i2){tmp=i0;i0=i2;i2=tmp;}
        if (i1>i3){tmp=i1;i1=i3;i3=tmp;}
        if (i1>i2){tmp=i1;i1=i2;i2=tmp;}
        g_idx[b*4+0]=i0; g_idx[b*4+1]=i1; g_idx[b*4+2]=i2; g_idx[b*4+3]=i3;
    }
}

// ---------------- fc1 (sparse gather GEMV) -> gelu -> g_a1 [2048,1024] ----------------
__global__ void __launch_bounds__(256) k_fc1(const float* __restrict__ w,
                                             const float* __restrict__ bias){
    int j = blockIdx.x*256 + threadIdx.x;
    int row = blockIdx.y;              // 0..2047 = b*4 + k
    if (j >= 1024) return;
    int b = row>>2, k = row&3;
    int id = g_idx[b*4+k];
    const float* xv = &g_x[(b*NO+id)*ND];
    float acc = bias[j];
    #pragma unroll
    for (int d=0; d<16; d++) acc += xv[d]*w[(id*16+d)*1024 + j];
    g_a1[row*1024 + j] = gelu_f(acc);
}

// ---------------- generic tiled fp32 GEMM over scratch buffers ----------------
template<int GELU, int HEAD>
__global__ void __launch_bounds__(256) k_gemm(const float* __restrict__ W,
                                              const float* __restrict__ bias,
                                              float* __restrict__ Cout,
                                              int K, int N, int sel){
    const float* A; float* C;
    switch (sel){
        case 0: A = g_a1; C = g_a2; break;
        case 1: A = g_a2; C = g_a3; break;
        case 2: A = g_a3; C = g_a4; break;
        case 3: A = g_a4; C = g_a5; break;
        default: A = g_a5; C = Cout; break;
    }
    __shared__ float As[16][64];
    __shared__ float Bs[16][64];
    int tid = threadIdx.x;
    int row0 = blockIdx.y*64, col0 = blockIdx.x*64;
    int tr = tid>>4, tc = tid&15;
    int lr = tid>>2,  lk4 = (tid&3)*4;
    int lkk = tid>>4, lc4 = (tid&15)*4;
    float acc[4][4];
    #pragma unroll
    for (int u=0;u<4;u++)
        #pragma unroll
        for (int v=0;v<4;v++) acc[u][v]=0.f;
    for (int k0=0; k0<K; k0+=16){
        float4 av = *(const float4*)&A[(size_t)(row0+lr)*K + k0 + lk4];
        As[lk4+0][lr]=av.x; As[lk4+1][lr]=av.y; As[lk4+2][lr]=av.z; As[lk4+3][lr]=av.w;
        float4 bv = *(const float4*)&W[(size_t)(k0+lkk)*N + col0 + lc4];
        *(float4*)&Bs[lkk][lc4] = bv;
        __syncthreads();
        #pragma unroll
        for (int kk=0; kk<16; kk++){
            float4 a4 = *(const float4*)&As[kk][tr*4];
            float4 b4 = *(const float4*)&Bs[kk][tc*4];
            acc[0][0] += a4.x*b4.x; acc[0][1] += a4.x*b4.y; acc[0][2] += a4.x*b4.z; acc[0][3] += a4.x*b4.w;
            acc[1][0] += a4.y*b4.x; acc[1][1] += a4.y*b4.y; acc[1][2] += a4.y*b4.z; acc[1][3] += a4.y*b4.w;
            acc[2][0] += a4.z*b4.x; acc[2][1] += a4.z*b4.y; acc[2][2] += a4.z*b4.z; acc[2][3] += a4.z*b4.w;
            acc[3][0] += a4.w*b4.x; acc[3][1] += a4.w*b4.y; acc[3][2] += a4.w*b4.z; acc[3][3] += a4.w*b4.w;
        }
        __syncthreads();
    }
    #pragma unroll
    for (int u=0;u<4;u++){
        int r = row0 + tr*4 + u;
        #pragma unroll
        for (int v=0;v<4;v++){
            int c = col0 + tc*4 + v;
            float val = acc[u][v] + bias[c];
            if (GELU) val = gelu_f(val);
            if (HEAD) C[(r>>2)*512 + c*4 + (r&3)] = val;  // out[b][a][k]
            else      C[(size_t)r*N + c] = val;
        }
    }
}

// ---------------- launch ----------------
extern "C" void kernel_launch(void* const* d_in, const int* in_sizes, int n_in,
                              void* d_out, int out_size){
    const float* scm     = (const float*)d_in[0];
    // d_in[1] = K (always 4 in this dataset)
    const float* w1 = (const float*)d_in[2];  const float* b1 = (const float*)d_in[3];
    const float* w2 = (const float*)d_in[4];  const float* b2 = (const float*)d_in[5];
    const float* w3 = (const float*)d_in[6];  const float* b3 = (const float*)d_in[7];
    const float* pw = (const float*)d_in[8];  const float* pb = (const float*)d_in[9];
    const float* capsW = (const float*)d_in[10];
    const float* capsB = (const float*)d_in[11];
    const float* f1w = (const float*)d_in[12]; const float* f1b = (const float*)d_in[13];
    const float* f2w = (const float*)d_in[14]; const float* f2b = (const float*)d_in[15];
    const float* f3w = (const float*)d_in[16]; const float* f3b = (const float*)d_in[17];
    const float* f4w = (const float*)d_in[18]; const float* f4b = (const float*)d_in[19];
    const float* f5w = (const float*)d_in[20]; const float* f5b = (const float*)d_in[21];
    const float* hw  = (const float*)d_in[22]; const float* hb  = (const float*)d_in[23];
    float* out = (float*)d_out;

    const int einsum_smem = 16*NI*20*4;  // 122880 B
    cudaFuncSetAttribute(k_einsum, cudaFuncAttributeMaxDynamicSharedMemorySize, einsum_smem);

    k_conv1<<<(NB*64*49 + 255)/256, 256>>>(scm, w1, b1);
    k_conv2<<<NB, 512>>>(w2, b2);
    k_conv3<<<NB, 1024>>>(w3, b3);
    k_pc   <<<NB, 384>>>(pw, pb);

    k_einsum<<<dim3(32, NO), 384, einsum_smem>>>(capsW);

    k_binit<<<(NB*BOI + 255)/256, 256>>>(capsB);
    for (int r=0; r<3; r++){
        k_softmax<<<(NB*NI + 255)/256, 256>>>();
        k_route<<<dim3(NO, NB), 96>>>(r==2 ? 1 : 0);
    }

    k_peaks<<<NB, 192>>>(out);

    k_fc1<<<dim3(4, 2048), 256>>>(f1w, f1b);
    k_gemm<1,0><<<dim3(12, 32), 256>>>(f2w, f2b, nullptr, 1024, 768, 0);
    k_gemm<1,0><<<dim3(8,  32), 256>>>(f3w, f3b, nullptr, 768,  512, 1);
    k_gemm<1,0><<<dim3(8,  32), 256>>>(f4w, f4b, nullptr, 512,  512, 2);
    k_gemm<1,0><<<dim3(4,  32), 256>>>(f5w, f5b, nullptr, 512,  256, 3);
    k_gemm<0,1><<<dim3(2,  32), 256>>>(hw,  hb,  out,     256,  128, 4);
    (void)in_sizes; (void)n_in; (void)out_size;
}

// round 5
// speedup vs baseline: 1.1440x; 1.1240x over previous
#include <cuda_runtime.h>
#include <cuda_fp16.h>

#define DEV_INLINE __device__ __forceinline__

// fully-inline erf (Abramowitz-Stegun 7.1.26, |err| <= 1.5e-7) -> exact-gelu
static DEV_INLINE float erf_inline(float x){
    float ax = fabsf(x);
    float t = __frcp_rn(fmaf(0.3275911f, ax, 1.0f));
    float y = fmaf(t, 1.061405429f, -1.453152027f);
    y = fmaf(t, y, 1.421413741f);
    y = fmaf(t, y, -0.284496736f);
    y = fmaf(t, y, 0.254829592f);
    y = y * t;
    float e = __expf(-ax*ax);
    float r = fmaf(-y, e, 1.0f);
    return copysignf(r, x);
}
static DEV_INLINE float gelu_f(float x){
    return 0.5f * x * (1.f + erf_inline(x * 0.70710678118654752440f));
}
static DEV_INLINE float exp_inline(float x){ return __expf(x); }

#define NB 512
#define NO 181
#define NI 96
#define ND 16
#define BOI (NO*NI)   // 17376

// ---------------- scratch (device globals; referenced ONLY from device code) ----------------
__device__ float  g_h1[NB*64*49];                 // conv1 out [b,ic,49]
__device__ float  g_col[1024*8192];               // im2col buffer (max 8.4M floats)
__device__ float  g_c2 [128*18432];               // conv2 out [oc, b*36+p]
__device__ float  g_c3 [256*12800];               // conv3 out [oc, b*25+p]
__device__ float  g_cp [96*8192];                 // pc conv out [oc, b*16+p]
__device__ float  g_u  [NB*NI*ND];
__device__ __half g_uhat[(size_t)NB*NO*NI*ND];    // 285 MB (fp16)
__device__ float  g_bmat[NB*BOI];
__device__ float  g_cmat[NB*BOI];
__device__ float  g_x  [NB*NO*ND];
__device__ int    g_idx[NB*4];
__device__ float  g_a1[2048*1024];
__device__ float  g_a2[2048*768];
__device__ float  g_a3[2048*512];
__device__ float  g_a4[2048*512];
__device__ float  g_a5[2048*256];

__device__ DEV_INLINE float* g_selbuf(int s){
    switch(s){
        case 0: return g_col;
        case 1: return g_c2;
        case 2: return g_c3;
        case 3: return g_cp;
        case 4: return g_a1;
        case 5: return g_a2;
        case 6: return g_a3;
        case 7: return g_a4;
        case 8: return g_a5;
    }
    return nullptr;
}

// ---------------- conv1: [512,3,8,8] -> gelu -> [512,64,7,7] ----------------
__global__ void __launch_bounds__(256) k_conv1(const float* __restrict__ x,
                                               const float* __restrict__ w,
                                               const float* __restrict__ bias){
    int idx = blockIdx.x*256 + threadIdx.x;
    if (idx >= NB*64*49) return;
    int p = idx % 49; int oc = (idx/49) & 63; int b = idx/(49*64);
    int y = p/7, xx = p%7;
    float acc = bias[oc];
    #pragma unroll
    for (int ci=0; ci<3; ci++){
        const float* xp = x + (b*3+ci)*64 + y*8 + xx;
        const float* wp = w + (oc*3+ci)*4;
        acc += xp[0]*wp[0] + xp[1]*wp[1] + xp[8]*wp[2] + xp[9]*wp[3];
    }
    g_h1[idx] = gelu_f(acc);
}

// ---------------- im2col from g_h1 [b,64,49] -> g_col [256][18432] ----------------
__global__ void __launch_bounds__(256) k_im2col_a(){
    int k = blockIdx.y;                 // 0..255 = ic*4+tap
    int n = blockIdx.x*256 + threadIdx.x;  // 0..18431 = b*36+p
    if (n >= 18432) return;
    int ic = k>>2, tap = k&3, dy = tap>>1, dx = tap&1;
    int b = n/36, p = n - b*36;
    int py = p/6, px = p - py*6;
    g_col[(size_t)k*18432 + n] = g_h1[((size_t)b*64+ic)*49 + (py+dy)*7 + (px+dx)];
}

// ---------------- im2col from sel buffer [CIN][NB*IPIX] -> g_col [K][Ntot] ----------------
__global__ void __launch_bounds__(256) k_im2col_b(int selSrc, int IPIX, int IW,
                                                  int OW, int OPIX, int Ntot){
    const float* src = g_selbuf(selSrc);
    int k = blockIdx.y;                 // ic*4+tap
    int n = blockIdx.x*256 + threadIdx.x;
    if (n >= Ntot) return;
    int ic = k>>2, tap = k&3, dy = tap>>1, dx = tap&1;
    int b = n/OPIX, p = n - b*OPIX;
    int py = p/OW, px = p - py*OW;
    g_col[(size_t)k*Ntot + n] = src[(size_t)ic*(NB*IPIX) + b*IPIX + (py+dy)*IW + (px+dx)];
}

// ---------------- unified tiled GEMM: C[M,N] = act(A[M,K] @ B[K,N] + bias) ----------------
// BM=64, BN=128, BK=16, 256 threads, 4x8 microtile.
// BIASM: bias indexed by M (conv weights) else by N (MLP). HEAD: transposed write.
template<int GELU, int HEAD, int BIASM>
__global__ void __launch_bounds__(256) k_bgemm(const float* __restrict__ Aext,
                                               const float* __restrict__ Bext,
                                               const float* __restrict__ bias,
                                               float* __restrict__ Cext,
                                               int M, int K, int N,
                                               int selA, int selB, int selC){
    const float* A = (selA < 0) ? Aext : (const float*)g_selbuf(selA);
    const float* B = (selB < 0) ? Bext : (const float*)g_selbuf(selB);
    float*       C = (selC < 0) ? Cext : g_selbuf(selC);
    __shared__ float As[16][64];
    __shared__ float Bs[16][128];
    int tid = threadIdx.x;
    int n0 = blockIdx.x*128, m0 = blockIdx.y*64;
    int tx = tid&15, ty = tid>>4;           // 16 x 16
    int aRow = tid>>2, aC4 = (tid&3)*4;     // A tile: 64x16 = 256 float4
    float acc[4][8];
    #pragma unroll
    for (int u=0;u<4;u++)
        #pragma unroll
        for (int v=0;v<8;v++) acc[u][v]=0.f;
    for (int k0=0; k0<K; k0+=16){
        int ar = m0 + aRow;
        float4 av = make_float4(0.f,0.f,0.f,0.f);
        if (ar < M) av = *(const float4*)&A[(size_t)ar*K + k0 + aC4];
        As[aC4+0][aRow]=av.x; As[aC4+1][aRow]=av.y;
        As[aC4+2][aRow]=av.z; As[aC4+3][aRow]=av.w;
        #pragma unroll
        for (int h=0; h<2; h++){
            int f = tid + h*256;
            int kr = f>>5, c4 = (f&31)*4;
            float4 bv = *(const float4*)&B[(size_t)(k0+kr)*N + n0 + c4];
            *(float4*)&Bs[kr][c4] = bv;
        }
        __syncthreads();
        #pragma unroll
        for (int kk=0; kk<16; kk++){
            float4 a4  = *(const float4*)&As[kk][ty*4];
            float4 b40 = *(const float4*)&Bs[kk][tx*8];
            float4 b41 = *(const float4*)&Bs[kk][tx*8+4];
            float a_[4] = {a4.x, a4.y, a4.z, a4.w};
            float b_[8] = {b40.x,b40.y,b40.z,b40.w, b41.x,b41.y,b41.z,b41.w};
            #pragma unroll
            for (int u=0;u<4;u++)
                #pragma unroll
                for (int v=0;v<8;v++) acc[u][v] = fmaf(a_[u], b_[v], acc[u][v]);
        }
        __syncthreads();
    }
    #pragma unroll
    for (int u=0;u<4;u++){
        int m = m0 + ty*4 + u;
        if (m >= M) continue;
        float bm = BIASM ? bias[m] : 0.f;
        #pragma unroll
        for (int v=0;v<8;v++){
            int c = n0 + tx*8 + v;
            float val = acc[u][v] + (BIASM ? bm : bias[c]);
            if (GELU) val = gelu_f(val);
            if (HEAD) C[(m>>2)*512 + c*4 + (m&3)] = val;   // out[b][a][k]
            else      C[(size_t)m*N + c] = val;
        }
    }
}

// ---------------- squash g_cp [96][512*16] -> g_u [b,96,16] ----------------
__global__ void __launch_bounds__(256) k_squash(){
    int e = blockIdx.x*256 + threadIdx.x;     // 96*512
    if (e >= NI*NB) return;
    int oc = e>>9, b = e&511;
    const float* src = &g_cp[(size_t)oc*8192 + b*16];
    float v[16];
    float nn = 0.f;
    #pragma unroll
    for (int p=0;p<16;p++){ v[p]=src[p]; nn += v[p]*v[p]; }
    float n = __fsqrt_rn(nn);
    float sc = (1.f - exp_inline(-n)) * __frcp_rn(n + 1e-8f);
    float* dst = &g_u[((size_t)b*NI+oc)*ND];
    #pragma unroll
    for (int p=0;p<16;p++) dst[p] = v[p]*sc;
}

// ---------------- einsum: u_hat[b,o,i,d] = sum_k W[o,i,d,k] u[b,i,k] (fp16 out) ----------------
__global__ void __launch_bounds__(384) k_einsum(const float* __restrict__ W){
    extern __shared__ float ush[];  // [16][96][20] padded
    int b0 = blockIdx.x * 16;
    int o  = blockIdx.y;
    int tid = threadIdx.x;
    for (int e=tid; e<16*NI*ND; e+=384){
        int bb = e/1536; int r = e - bb*1536; int i = r>>4; int k = r&15;
        ush[(bb*NI+i)*20 + k] = g_u[(b0+bb)*1536 + r];
    }
    __syncthreads();
    int i = tid>>2, dq = tid&3;
    const float4* Wv = (const float4*)(W + ((size_t)(o*NI + i)*ND + dq*4)*ND);
    float4 wr[16];
    #pragma unroll
    for (int t=0;t<16;t++) wr[t]=Wv[t];
    #pragma unroll 4
    for (int bb=0; bb<16; bb++){
        const float* ub = &ush[(bb*NI+i)*20];
        float4 u0=*(const float4*)(ub), u1=*(const float4*)(ub+4),
               u2=*(const float4*)(ub+8), u3=*(const float4*)(ub+12);
        float a0, a1, a2, a3;
        {
            float4 wa=wr[0], wb=wr[1], wc=wr[2], wd=wr[3];
            a0 = wa.x*u0.x + wa.y*u0.y + wa.z*u0.z + wa.w*u0.w
               + wb.x*u1.x + wb.y*u1.y + wb.z*u1.z + wb.w*u1.w
               + wc.x*u2.x + wc.y*u2.y + wc.z*u2.z + wc.w*u2.w
               + wd.x*u3.x + wd.y*u3.y + wd.z*u3.z + wd.w*u3.w;
        }
        {
            float4 wa=wr[4], wb=wr[5], wc=wr[6], wd=wr[7];
            a1 = wa.x*u0.x + wa.y*u0.y + wa.z*u0.z + wa.w*u0.w
               + wb.x*u1.x + wb.y*u1.y + wb.z*u1.z + wb.w*u1.w
               + wc.x*u2.x + wc.y*u2.y + wc.z*u2.z + wc.w*u2.w
               + wd.x*u3.x + wd.y*u3.y + wd.z*u3.z + wd.w*u3.w;
        }
        {
            float4 wa=wr[8], wb=wr[9], wc=wr[10], wd=wr[11];
            a2 = wa.x*u0.x + wa.y*u0.y + wa.z*u0.z + wa.w*u0.w
               + wb.x*u1.x + wb.y*u1.y + wb.z*u1.z + wb.w*u1.w
               + wc.x*u2.x + wc.y*u2.y + wc.z*u2.z + wc.w*u2.w
               + wd.x*u3.x + wd.y*u3.y + wd.z*u3.z + wd.w*u3.w;
        }
        {
            float4 wa=wr[12], wb=wr[13], wc=wr[14], wd=wr[15];
            a3 = wa.x*u0.x + wa.y*u0.y + wa.z*u0.z + wa.w*u0.w
               + wb.x*u1.x + wb.y*u1.y + wb.z*u1.z + wb.w*u1.w
               + wc.x*u2.x + wc.y*u2.y + wc.z*u2.z + wc.w*u2.w
               + wd.x*u3.x + wd.y*u3.y + wd.z*u3.z + wd.w*u3.w;
        }
        __half2 p0 = __floats2half2_rn(a0, a1);
        __half2 p1 = __floats2half2_rn(a2, a3);
        size_t base = (((size_t)(b0+bb)*NO + o)*NI + i)*ND + dq*4;
        *(__half2*)&g_uhat[base]     = p0;
        *(__half2*)&g_uhat[base + 2] = p1;
    }
}

// ---------------- routing ----------------
__global__ void __launch_bounds__(256) k_binit(const float* __restrict__ caps_b){
    int t = blockIdx.x*256 + threadIdx.x;
    if (t < NB*BOI) g_bmat[t] = caps_b[t % BOI];
}

__global__ void __launch_bounds__(256) k_softmax(){
    int t = blockIdx.x*256 + threadIdx.x;
    if (t >= NB*NI) return;
    int b = t/NI, i = t - (t/NI)*NI;
    const float* p = g_bmat + b*BOI + i;
    float mx = -1e30f;
    for (int o=0;o<NO;o++) mx = fmaxf(mx, p[o*NI]);
    float sum = 0.f;
    for (int o=0;o<NO;o++) sum += exp_inline(p[o*NI]-mx);
    float inv = __frcp_rn(sum);
    float* cp = g_cmat + b*BOI + i;
    for (int o=0;o<NO;o++) cp[o*NI] = exp_inline(p[o*NI]-mx)*inv;
}

__global__ void __launch_bounds__(96) k_route(int last){
    int o = blockIdx.x, b = blockIdx.y;
    int i = threadIdx.x;
    __shared__ float part[3][16];
    __shared__ float vsh[16];
    size_t base = (((size_t)b*NO+o)*NI + i)*ND;
    float4 raw0 = *(const float4*)&g_uhat[base];
    float4 raw1 = *(const float4*)&g_uhat[base + 8];
    float h[16];
    {
        const __half2* q = (const __half2*)&raw0;
        #pragma unroll
        for (int t=0;t<4;t++){ float2 f = __half22float2(q[t]); h[t*2]=f.x; h[t*2+1]=f.y; }
        const __half2* q2 = (const __half2*)&raw1;
        #pragma unroll
        for (int t=0;t<4;t++){ float2 f = __half22float2(q2[t]); h[8+t*2]=f.x; h[8+t*2+1]=f.y; }
    }
    float ci = g_cmat[b*BOI + o*NI + i];
    float wv[16];
    #pragma unroll
    for (int d=0;d<16;d++) wv[d] = ci*h[d];
    #pragma unroll
    for (int off=16; off>0; off>>=1){
        #pragma unroll
        for (int d=0; d<16; d++) wv[d] += __shfl_down_sync(0xffffffffu, wv[d], off);
    }
    int warp = i>>5, lane = i&31;
    if (lane==0){
        #pragma unroll
        for (int d=0; d<16; d++) part[warp][d]=wv[d];
    }
    __syncthreads();
    if (i<16){
        float s = part[0][i]+part[1][i]+part[2][i];
        float nn = s*s;
        #pragma unroll
        for (int off=8; off>0; off>>=1) nn += __shfl_xor_sync(0x0000ffffu, nn, off);
        float n = __fsqrt_rn(nn);
        float sc = (1.f - exp_inline(-n)) * __frcp_rn(n + 1e-8f);
        float vd = s*sc;
        vsh[i]=vd;
        if (last) g_x[(b*NO+o)*ND + i] = vd;
    }
    __syncthreads();
    if (!last){
        float dot = 0.f;
        #pragma unroll
        for (int d=0;d<16;d++) dot += vsh[d]*h[d];
        g_bmat[b*BOI + o*NI + i] += dot;
    }
}

// ---------------- length, normalize, peak-pick top4 ----------------
__global__ void __launch_bounds__(192) k_peaks(float* __restrict__ d_out){
    __shared__ float len[192];
    __shared__ float pk[192];
    __shared__ float s_sum;
    int b = blockIdx.x, t = threadIdx.x;
    float n = 0.f;
    if (t < NO){
        const float4* xp = (const float4*)&g_x[(b*NO+t)*ND];
        float4 a=xp[0], b4=xp[1], c=xp[2], d=xp[3];
        float nn = a.x*a.x+a.y*a.y+a.z*a.z+a.w*a.w
                 + b4.x*b4.x+b4.y*b4.y+b4.z*b4.z+b4.w*b4.w
                 + c.x*c.x+c.y*c.y+c.z*c.z+c.w*c.w
                 + d.x*d.x+d.y*d.y+d.z*d.z+d.w*d.w;
        n = __fsqrt_rn(nn);
    }
    len[t] = (t < NO) ? n : 0.f;
    __syncthreads();
    if (t==0){
        float s=0.f;
        for (int o=0;o<NO;o++) s+=len[o];
        s_sum = s + 1e-8f;
    }
    __syncthreads();
    if (t < NO) len[t] = len[t]/s_sum;
    __syncthreads();
    if (t < NO){
        float m = -1e30f;
        #pragma unroll
        for (int dd=-5; dd<=5; dd++){
            int oo = t+dd;
            if (oo>=0 && oo<NO) m = fmaxf(m, len[oo]);
        }
        pk[t] = (len[t]==m) ? len[t] : 0.f;
        d_out[NB*128*4 + b*NO + t] = len[t];
    }
    __syncthreads();
    if (t==0){
        int i0, i1, i2, i3;
        {
            float bv=-1.f; int bi=0;
            for (int o=0;o<NO;o++){ float v=pk[o]; if (v>bv){ bv=v; bi=o; } }
            i0=bi; pk[bi]=-2.f;
        }
        {
            float bv=-1.f; int bi=0;
            for (int o=0;o<NO;o++){ float v=pk[o]; if (v>bv){ bv=v; bi=o; } }
            i1=bi; pk[bi]=-2.f;
        }
        {
            float bv=-1.f; int bi=0;
            for (int o=0;o<NO;o++){ float v=pk[o]; if (v>bv){ bv=v; bi=o; } }
            i2=bi; pk[bi]=-2.f;
        }
        {
            float bv=-1.f; int bi=0;
            for (int o=0;o<NO;o++){ float v=pk[o]; if (v>bv){ bv=v; bi=o; } }
            i3=bi;
        }
        int tmp;
        if (i0>i1){tmp=i0;i0=i1;i1=tmp;}
        if (i2>i3){tmp=i2;i2=i3;i3=tmp;}
        if (i0>i2){tmp=i0;i0=i2;i2=tmp;}
        if (i1>i3){tmp=i1;i1=i3;i3=tmp;}
        if (i1>i2){tmp=i1;i1=i2;i2=tmp;}
        g_idx[b*4+0]=i0; g_idx[b*4+1]=i1; g_idx[b*4+2]=i2; g_idx[b*4+3]=i3;
    }
}

// ---------------- fc1 (sparse gather GEMV) -> gelu -> g_a1 [2048,1024] ----------------
__global__ void __launch_bounds__(256) k_fc1(const float* __restrict__ w,
                                             const float* __restrict__ bias){
    int j = blockIdx.x*256 + threadIdx.x;
    int row = blockIdx.y;
    if (j >= 1024) return;
    int b = row>>2, k = row&3;
    int id = g_idx[b*4+k];
    const float* xv = &g_x[(b*NO+id)*ND];
    float acc = bias[j];
    #pragma unroll
    for (int d=0; d<16; d++) acc += xv[d]*w[(id*16+d)*1024 + j];
    g_a1[row*1024 + j] = gelu_f(acc);
}

// ---------------- launch ----------------
extern "C" void kernel_launch(void* const* d_in, const int* in_sizes, int n_in,
                              void* d_out, int out_size){
    const float* scm     = (const float*)d_in[0];
    const float* w1 = (const float*)d_in[2];  const float* b1 = (const float*)d_in[3];
    const float* w2 = (const float*)d_in[4];  const float* b2 = (const float*)d_in[5];
    const float* w3 = (const float*)d_in[6];  const float* b3 = (const float*)d_in[7];
    const float* pw = (const float*)d_in[8];  const float* pb = (const float*)d_in[9];
    const float* capsW = (const float*)d_in[10];
    const float* capsB = (const float*)d_in[11];
    const float* f1w = (const float*)d_in[12]; const float* f1b = (const float*)d_in[13];
    const float* f2w = (const float*)d_in[14]; const float* f2b = (const float*)d_in[15];
    const float* f3w = (const float*)d_in[16]; const float* f3b = (const float*)d_in[17];
    const float* f4w = (const float*)d_in[18]; const float* f4b = (const float*)d_in[19];
    const float* f5w = (const float*)d_in[20]; const float* f5b = (const float*)d_in[21];
    const float* hw  = (const float*)d_in[22]; const float* hb  = (const float*)d_in[23];
    float* out = (float*)d_out;

    const int einsum_smem = 16*NI*20*4;  // 122880 B
    cudaFuncSetAttribute(k_einsum, cudaFuncAttributeMaxDynamicSharedMemorySize, einsum_smem);

    // conv stack as im2col + GEMM
    k_conv1<<<(NB*64*49 + 255)/256, 256>>>(scm, w1, b1);
    k_im2col_a<<<dim3(72, 256), 256>>>();
    k_bgemm<1,0,1><<<dim3(144, 2), 256>>>(w2, nullptr, b2, nullptr, 128, 256, 18432, -1, 0, 1);
    k_im2col_b<<<dim3(50, 512), 256>>>(1, 36, 6, 5, 25, 12800);
    k_bgemm<1,0,1><<<dim3(100, 4), 256>>>(w3, nullptr, b3, nullptr, 256, 512, 12800, -1, 0, 2);
    k_im2col_b<<<dim3(32, 1024), 256>>>(2, 25, 5, 4, 16, 8192);
    k_bgemm<0,0,1><<<dim3(64, 2), 256>>>(pw, nullptr, pb, nullptr, 96, 1024, 8192, -1, 0, 3);
    k_squash<<<(NI*NB + 255)/256, 256>>>();

    // capsule layer
    k_einsum<<<dim3(32, NO), 384, einsum_smem>>>(capsW);
    k_binit<<<(NB*BOI + 255)/256, 256>>>(capsB);
    for (int r=0; r<3; r++){
        k_softmax<<<(NB*NI + 255)/256, 256>>>();
        k_route<<<dim3(NO, NB), 96>>>(r==2 ? 1 : 0);
    }
    k_peaks<<<NB, 192>>>(out);

    // MLP tail
    k_fc1<<<dim3(4, 2048), 256>>>(f1w, f1b);
    k_bgemm<1,0,0><<<dim3(6, 32), 256>>>(nullptr, f2w, f2b, nullptr, 2048, 1024, 768, 4, -1, 5);
    k_bgemm<1,0,0><<<dim3(4, 32), 256>>>(nullptr, f3w, f3b, nullptr, 2048, 768,  512, 5, -1, 6);
    k_bgemm<1,0,0><<<dim3(4, 32), 256>>>(nullptr, f4w, f4b, nullptr, 2048, 512,  512, 6, -1, 7);
    k_bgemm<1,0,0><<<dim3(2, 32), 256>>>(nullptr, f5w, f5b, nullptr, 2048, 512,  256, 7, -1, 8);
    k_bgemm<0,1,0><<<dim3(1, 32), 256>>>(nullptr, hw,  hb,  out,     2048, 256,  128, 8, -1, -1);
    (void)in_sizes; (void)n_in; (void)out_size;
}

// round 7
// speedup vs baseline: 1.3184x; 1.1525x over previous
#include <cuda_runtime.h>
#include <cuda_fp16.h>

#define DEV_INLINE __device__ __forceinline__

// fully-inline erf (Abramowitz-Stegun 7.1.26, |err| <= 1.5e-7) -> exact-gelu
static DEV_INLINE float erf_inline(float x){
    float ax = fabsf(x);
    float t = __frcp_rn(fmaf(0.3275911f, ax, 1.0f));
    float y = fmaf(t, 1.061405429f, -1.453152027f);
    y = fmaf(t, y, 1.421413741f);
    y = fmaf(t, y, -0.284496736f);
    y = fmaf(t, y, 0.254829592f);
    y = y * t;
    float e = __expf(-ax*ax);
    float r = fmaf(-y, e, 1.0f);
    return copysignf(r, x);
}
static DEV_INLINE float gelu_f(float x){
    return 0.5f * x * (1.f + erf_inline(x * 0.70710678118654752440f));
}
static DEV_INLINE float exp_inline(float x){ return __expf(x); }

#define NB 512
#define NO 181
#define NI 96
#define ND 16
#define BOI (NO*NI)   // 17376

// ---------------- scratch (device globals; referenced ONLY from device code) ----------------
__device__ float  g_h1[NB*64*49];                 // conv1 out [b,ic,49]
__device__ float  g_col[1024*8192];               // im2col buffer
__device__ float  g_c2 [128*18432];               // conv2 out [oc, b*36+p]
__device__ float  g_c3 [256*12800];               // conv3 out [oc, b*25+p]
__device__ float  g_cp [96*8192];                 // pc conv out [oc, b*16+p]
__device__ float  g_u  [NB*NI*ND];
__device__ __half g_uhat[(size_t)NB*NO*NI*ND];    // 285 MB (fp16)
__device__ float  g_x  [NB*NO*ND];
__device__ int    g_idx[NB*4];
__device__ float  g_a1[2048*1024];
__device__ float  g_a2[2048*768];
__device__ float  g_a3[2048*512];
__device__ float  g_a4[2048*512];
__device__ float  g_a5[2048*256];

__device__ DEV_INLINE float* g_selbuf(int s){
    switch(s){
        case 0: return g_col;
        case 1: return g_c2;
        case 2: return g_c3;
        case 3: return g_cp;
        case 4: return g_a1;
        case 5: return g_a2;
        case 6: return g_a3;
        case 7: return g_a4;
        case 8: return g_a5;
    }
    return nullptr;
}

// ---------------- conv1: [512,3,8,8] -> gelu -> [512,64,7,7] ----------------
__global__ void __launch_bounds__(256) k_conv1(const float* __restrict__ x,
                                               const float* __restrict__ w,
                                               const float* __restrict__ bias){
    int idx = blockIdx.x*256 + threadIdx.x;
    if (idx >= NB*64*49) return;
    int p = idx % 49; int oc = (idx/49) & 63; int b = idx/(49*64);
    int y = p/7, xx = p%7;
    float acc = bias[oc];
    #pragma unroll
    for (int ci=0; ci<3; ci++){
        const float* xp = x + (b*3+ci)*64 + y*8 + xx;
        const float* wp = w + (oc*3+ci)*4;
        acc += xp[0]*wp[0] + xp[1]*wp[1] + xp[8]*wp[2] + xp[9]*wp[3];
    }
    g_h1[idx] = gelu_f(acc);
}

// ---------------- im2col from g_h1 [b,64,49] -> g_col [256][18432] ----------------
__global__ void __launch_bounds__(256) k_im2col_a(){
    int k = blockIdx.y;
    int n = blockIdx.x*256 + threadIdx.x;
    if (n >= 18432) return;
    int ic = k>>2, tap = k&3, dy = tap>>1, dx = tap&1;
    int b = n/36, p = n - b*36;
    int py = p/6, px = p - py*6;
    g_col[(size_t)k*18432 + n] = g_h1[((size_t)b*64+ic)*49 + (py+dy)*7 + (px+dx)];
}

// ---------------- im2col from sel buffer [CIN][NB*IPIX] -> g_col [K][Ntot] ----------------
__global__ void __launch_bounds__(256) k_im2col_b(int selSrc, int IPIX, int IW,
                                                  int OW, int OPIX, int Ntot){
    const float* src = g_selbuf(selSrc);
    int k = blockIdx.y;
    int n = blockIdx.x*256 + threadIdx.x;
    if (n >= Ntot) return;
    int ic = k>>2, tap = k&3, dy = tap>>1, dx = tap&1;
    int b = n/OPIX, p = n - b*OPIX;
    int py = p/OW, px = p - py*OW;
    g_col[(size_t)k*Ntot + n] = src[(size_t)ic*(NB*IPIX) + b*IPIX + (py+dy)*IW + (px+dx)];
}

// ---------------- unified tiled GEMM: C[M,N] = act(A[M,K] @ B[K,N] + bias) ----------------
template<int GELU, int HEAD, int BIASM>
__global__ void __launch_bounds__(256) k_bgemm(const float* __restrict__ Aext,
                                               const float* __restrict__ Bext,
                                               const float* __restrict__ bias,
                                               float* __restrict__ Cext,
                                               int M, int K, int N,
                                               int selA, int selB, int selC){
    const float* A = (selA < 0) ? Aext : (const float*)g_selbuf(selA);
    const float* B = (selB < 0) ? Bext : (const float*)g_selbuf(selB);
    float*       C = (selC < 0) ? Cext : g_selbuf(selC);
    __shared__ float As[16][64];
    __shared__ float Bs[16][128];
    int tid = threadIdx.x;
    int n0 = blockIdx.x*128, m0 = blockIdx.y*64;
    int tx = tid&15, ty = tid>>4;
    int aRow = tid>>2, aC4 = (tid&3)*4;
    float acc[4][8];
    #pragma unroll
    for (int u=0;u<4;u++)
        #pragma unroll
        for (int v=0;v<8;v++) acc[u][v]=0.f;
    for (int k0=0; k0<K; k0+=16){
        int ar = m0 + aRow;
        float4 av = make_float4(0.f,0.f,0.f,0.f);
        if (ar < M) av = *(const float4*)&A[(size_t)ar*K + k0 + aC4];
        As[aC4+0][aRow]=av.x; As[aC4+1][aRow]=av.y;
        As[aC4+2][aRow]=av.z; As[aC4+3][aRow]=av.w;
        #pragma unroll
        for (int h=0; h<2; h++){
            int f = tid + h*256;
            int kr = f>>5, c4 = (f&31)*4;
            float4 bv = *(const float4*)&B[(size_t)(k0+kr)*N + n0 + c4];
            *(float4*)&Bs[kr][c4] = bv;
        }
        __syncthreads();
        #pragma unroll
        for (int kk=0; kk<16; kk++){
            float4 a4  = *(const float4*)&As[kk][ty*4];
            float4 b40 = *(const float4*)&Bs[kk][tx*8];
            float4 b41 = *(const float4*)&Bs[kk][tx*8+4];
            float a_[4] = {a4.x, a4.y, a4.z, a4.w};
            float b_[8] = {b40.x,b40.y,b40.z,b40.w, b41.x,b41.y,b41.z,b41.w};
            #pragma unroll
            for (int u=0;u<4;u++)
                #pragma unroll
                for (int v=0;v<8;v++) acc[u][v] = fmaf(a_[u], b_[v], acc[u][v]);
        }
        __syncthreads();
    }
    #pragma unroll
    for (int u=0;u<4;u++){
        int m = m0 + ty*4 + u;
        if (m >= M) continue;
        float bm = BIASM ? bias[m] : 0.f;
        #pragma unroll
        for (int v=0;v<8;v++){
            int c = n0 + tx*8 + v;
            float val = acc[u][v] + (BIASM ? bm : bias[c]);
            if (GELU) val = gelu_f(val);
            if (HEAD) C[(m>>2)*512 + c*4 + (m&3)] = val;
            else      C[(size_t)m*N + c] = val;
        }
    }
}

// ---------------- squash g_cp [96][512*16] -> g_u [b,96,16] ----------------
__global__ void __launch_bounds__(256) k_squash(){
    int e = blockIdx.x*256 + threadIdx.x;
    if (e >= NI*NB) return;
    int oc = e>>9, b = e&511;
    const float* src = &g_cp[(size_t)oc*8192 + b*16];
    float v[16];
    float nn = 0.f;
    #pragma unroll
    for (int p=0;p<16;p++){ v[p]=src[p]; nn += v[p]*v[p]; }
    float n = __fsqrt_rn(nn);
    float sc = (1.f - exp_inline(-n)) * __frcp_rn(n + 1e-8f);
    float* dst = &g_u[((size_t)b*NI+oc)*ND];
    #pragma unroll
    for (int p=0;p<16;p++) dst[p] = v[p]*sc;
}

// ---------------- einsum: u_hat[b,o,i,d] = sum_k W[o,i,d,k] u[b,i,k] (fp16 out) ----------------
__global__ void __launch_bounds__(384) k_einsum(const float* __restrict__ W){
    extern __shared__ float ush[];
    int b0 = blockIdx.x * 16;
    int o  = blockIdx.y;
    int tid = threadIdx.x;
    for (int e=tid; e<16*NI*ND; e+=384){
        int bb = e/1536; int r = e - bb*1536; int i = r>>4; int k = r&15;
        ush[(bb*NI+i)*20 + k] = g_u[(b0+bb)*1536 + r];
    }
    __syncthreads();
    int i = tid>>2, dq = tid&3;
    const float4* Wv = (const float4*)(W + ((size_t)(o*NI + i)*ND + dq*4)*ND);
    float4 wr[16];
    #pragma unroll
    for (int t=0;t<16;t++) wr[t]=Wv[t];
    #pragma unroll 4
    for (int bb=0; bb<16; bb++){
        const float* ub = &ush[(bb*NI+i)*20];
        float4 u0=*(const float4*)(ub), u1=*(const float4*)(ub+4),
               u2=*(const float4*)(ub+8), u3=*(const float4*)(ub+12);
        float a0, a1, a2, a3;
        {
            float4 wa=wr[0], wb=wr[1], wc=wr[2], wd=wr[3];
            a0 = wa.x*u0.x + wa.y*u0.y + wa.z*u0.z + wa.w*u0.w
               + wb.x*u1.x + wb.y*u1.y + wb.z*u1.z + wb.w*u1.w
               + wc.x*u2.x + wc.y*u2.y + wc.z*u2.z + wc.w*u2.w
               + wd.x*u3.x + wd.y*u3.y + wd.z*u3.z + wd.w*u3.w;
        }
        {
            float4 wa=wr[4], wb=wr[5], wc=wr[6], wd=wr[7];
            a1 = wa.x*u0.x + wa.y*u0.y + wa.z*u0.z + wa.w*u0.w
               + wb.x*u1.x + wb.y*u1.y + wb.z*u1.z + wb.w*u1.w
               + wc.x*u2.x + wc.y*u2.y + wc.z*u2.z + wc.w*u2.w
               + wd.x*u3.x + wd.y*u3.y + wd.z*u3.z + wd.w*u3.w;
        }
        {
            float4 wa=wr[8], wb=wr[9], wc=wr[10], wd=wr[11];
            a2 = wa.x*u0.x + wa.y*u0.y + wa.z*u0.z + wa.w*u0.w
               + wb.x*u1.x + wb.y*u1.y + wb.z*u1.z + wb.w*u1.w
               + wc.x*u2.x + wc.y*u2.y + wc.z*u2.z + wc.w*u2.w
               + wd.x*u3.x + wd.y*u3.y + wd.z*u3.z + wd.w*u3.w;
        }
        {
            float4 wa=wr[12], wb=wr[13], wc=wr[14], wd=wr[15];
            a3 = wa.x*u0.x + wa.y*u0.y + wa.z*u0.z + wa.w*u0.w
               + wb.x*u1.x + wb.y*u1.y + wb.z*u1.z + wb.w*u1.w
               + wc.x*u2.x + wc.y*u2.y + wc.z*u2.z + wc.w*u2.w
               + wd.x*u3.x + wd.y*u3.y + wd.z*u3.z + wd.w*u3.w;
        }
        __half2 p0 = __floats2half2_rn(a0, a1);
        __half2 p1 = __floats2half2_rn(a2, a3);
        size_t base = (((size_t)(b0+bb)*NO + o)*NI + i)*ND + dq*4;
        *(__half2*)&g_uhat[base]     = p0;
        *(__half2*)&g_uhat[base + 2] = p1;
    }
}

// ---------------- fused routing: 3 iterations + softmax + peaks; one block per b ----------------
// smem: bm[17376] | mx[96] | inv[96] | red[384] | len[192] | pk[192]  (73.3KB; padded to force 1 blk/SM)
__global__ void __launch_bounds__(512) k_routefuse(const float* __restrict__ caps_b,
                                                   float* __restrict__ d_out){
    extern __shared__ float sm[];
    float* bm  = sm;
    float* mx  = sm + 17376;
    float* inv = sm + 17472;
    float* red = sm + 17568;
    float* len = sm + 17952;
    float* pk  = sm + 18144;
    __shared__ float s_sum;
    int b = blockIdx.x;
    int t = threadIdx.x;
    for (int e=t; e<BOI; e+=512) bm[e] = caps_b[e];
    if (t < 192) len[t] = 0.f;
    __syncthreads();
    int wid = t>>5, lane = t&31;
    int i0 = lane*3;
    for (int iter=0; iter<3; iter++){
        // ---- softmax stats over o, per i (96 x 4 reduction groups) ----
        if (t < 384){
            int i = t % 96, g = t / 96;
            float m = -1e30f;
            for (int o=g; o<NO; o+=4) m = fmaxf(m, bm[o*96+i]);
            red[g*96+i] = m;
        }
        __syncthreads();
        if (t < 96) mx[t] = fmaxf(fmaxf(red[t], red[96+t]), fmaxf(red[192+t], red[288+t]));
        __syncthreads();
        if (t < 384){
            int i = t % 96, g = t / 96;
            float m = mx[i];
            float s = 0.f;
            for (int o=g; o<NO; o+=4) s += __expf(bm[o*96+i] - m);
            red[g*96+i] = s;
        }
        __syncthreads();
        if (t < 96) inv[t] = __frcp_rn(red[t]+red[96+t]+red[192+t]+red[288+t]);
        __syncthreads();
        // ---- warp per o: weighted sum over i, squash, b-update or output ----
        int last = (iter==2);
        for (int o=wid; o<NO; o+=16){
            const float4* hp = (const float4*)(g_uhat + ((size_t)b*NO + o)*1536 + lane*48);
            float hf[48];
            #pragma unroll
            for (int q=0;q<6;q++){
                float4 r4 = hp[q];
                const __half2* hh = (const __half2*)&r4;
                #pragma unroll
                for (int x=0;x<4;x++){
                    float2 f = __half22float2(hh[x]);
                    hf[q*8+x*2]   = f.x;
                    hf[q*8+x*2+1] = f.y;
                }
            }
            float c0 = __expf(bm[o*96+i0  ] - mx[i0  ]) * inv[i0  ];
            float c1 = __expf(bm[o*96+i0+1] - mx[i0+1]) * inv[i0+1];
            float c2 = __expf(bm[o*96+i0+2] - mx[i0+2]) * inv[i0+2];
            float S[16];
            #pragma unroll
            for (int d=0;d<16;d++)
                S[d] = c0*hf[d] + c1*hf[16+d] + c2*hf[32+d];
            #pragma unroll
            for (int off=16; off>0; off>>=1){
                #pragma unroll
                for (int d=0;d<16;d++) S[d] += __shfl_xor_sync(0xffffffffu, S[d], off);
            }
            float nn = 0.f;
            #pragma unroll
            for (int d=0;d<16;d++) nn += S[d]*S[d];
            float n = __fsqrt_rn(nn);
            float sc = (1.f - __expf(-n)) * __frcp_rn(n + 1e-8f);
            if (!last){
                float d0=0.f, d1=0.f, d2=0.f;
                #pragma unroll
                for (int d=0;d<16;d++){
                    float vd = S[d]*sc;
                    d0 = fmaf(vd, hf[d],    d0);
                    d1 = fmaf(vd, hf[16+d], d1);
                    d2 = fmaf(vd, hf[32+d], d2);
                }
                bm[o*96+i0  ] += d0;
                bm[o*96+i0+1] += d1;
                bm[o*96+i0+2] += d2;
            } else {
                if (lane < 16) g_x[((size_t)b*NO+o)*ND + lane] = S[lane]*sc;
                if (lane == 0) len[o] = n*sc;
            }
        }
        __syncthreads();
    }
    // ---- peaks epilogue ----
    if (t==0){
        float s=0.f;
        for (int o=0;o<NO;o++) s+=len[o];
        s_sum = s + 1e-8f;
    }
    __syncthreads();
    if (t < NO) len[t] = len[t] / s_sum;
    __syncthreads();
    if (t < NO){
        float m = -1e30f;
        #pragma unroll
        for (int dd=-5; dd<=5; dd++){
            int oo = t+dd;
            if (oo>=0 && oo<NO) m = fmaxf(m, len[oo]);
        }
        pk[t] = (len[t]==m) ? len[t] : 0.f;
        d_out[NB*128*4 + b*NO + t] = len[t];
    } else if (t < 192) pk[t] = 0.f;
    __syncthreads();
    if (t==0){
        int i0s, i1s, i2s, i3s;
        {
            float bv=-1.f; int bi=0;
            for (int o=0;o<NO;o++){ float v=pk[o]; if (v>bv){ bv=v; bi=o; } }
            i0s=bi; pk[bi]=-2.f;
        }
        {
            float bv=-1.f; int bi=0;
            for (int o=0;o<NO;o++){ float v=pk[o]; if (v>bv){ bv=v; bi=o; } }
            i1s=bi; pk[bi]=-2.f;
        }
        {
            float bv=-1.f; int bi=0;
            for (int o=0;o<NO;o++){ float v=pk[o]; if (v>bv){ bv=v; bi=o; } }
            i2s=bi; pk[bi]=-2.f;
        }
        {
            float bv=-1.f; int bi=0;
            for (int o=0;o<NO;o++){ float v=pk[o]; if (v>bv){ bv=v; bi=o; } }
            i3s=bi;
        }
        int tmp;
        if (i0s>i1s){tmp=i0s;i0s=i1s;i1s=tmp;}
        if (i2s>i3s){tmp=i2s;i2s=i3s;i3s=tmp;}
        if (i0s>i2s){tmp=i0s;i0s=i2s;i2s=tmp;}
        if (i1s>i3s){tmp=i1s;i1s=i3s;i3s=tmp;}
        if (i1s>i2s){tmp=i1s;i1s=i2s;i2s=tmp;}
        g_idx[b*4+0]=i0s; g_idx[b*4+1]=i1s; g_idx[b*4+2]=i2s; g_idx[b*4+3]=i3s;
    }
}

// ---------------- fc1 (sparse gather GEMV) -> gelu -> g_a1 [2048,1024] ----------------
__global__ void __launch_bounds__(256) k_fc1(const float* __restrict__ w,
                                             const float* __restrict__ bias){
    int j = blockIdx.x*256 + threadIdx.x;
    int row = blockIdx.y;
    if (j >= 1024) return;
    int b = row>>2, k = row&3;
    int id = g_idx[b*4+k];
    const float* xv = &g_x[(b*NO+id)*ND];
    float acc = bias[j];
    #pragma unroll
    for (int d=0; d<16; d++) acc += xv[d]*w[(id*16+d)*1024 + j];
    g_a1[row*1024 + j] = gelu_f(acc);
}

// ---------------- launch ----------------
extern "C" void kernel_launch(void* const* d_in, const int* in_sizes, int n_in,
                              void* d_out, int out_size){
    const float* scm     = (const float*)d_in[0];
    const float* w1 = (const float*)d_in[2];  const float* b1 = (const float*)d_in[3];
    const float* w2 = (const float*)d_in[4];  const float* b2 = (const float*)d_in[5];
    const float* w3 = (const float*)d_in[6];  const float* b3 = (const float*)d_in[7];
    const float* pw = (const float*)d_in[8];  const float* pb = (const float*)d_in[9];
    const float* capsW = (const float*)d_in[10];
    const float* capsB = (const float*)d_in[11];
    const float* f1w = (const float*)d_in[12]; const float* f1b = (const float*)d_in[13];
    const float* f2w = (const float*)d_in[14]; const float* f2b = (const float*)d_in[15];
    const float* f3w = (const float*)d_in[16]; const float* f3b = (const float*)d_in[17];
    const float* f4w = (const float*)d_in[18]; const float* f4b = (const float*)d_in[19];
    const float* f5w = (const float*)d_in[20]; const float* f5b = (const float*)d_in[21];
    const float* hw  = (const float*)d_in[22]; const float* hb  = (const float*)d_in[23];
    float* out = (float*)d_out;

    const int einsum_smem = 16*NI*20*4;   // 122880 B
    const int route_smem  = 120*1024;     // pad to force 1 block/SM (L2 residency)
    cudaFuncSetAttribute(k_einsum,    cudaFuncAttributeMaxDynamicSharedMemorySize, einsum_smem);
    cudaFuncSetAttribute(k_routefuse, cudaFuncAttributeMaxDynamicSharedMemorySize, route_smem);

    // conv stack as im2col + GEMM
    k_conv1<<<(NB*64*49 + 255)/256, 256>>>(scm, w1, b1);
    k_im2col_a<<<dim3(72, 256), 256>>>();
    k_bgemm<1,0,1><<<dim3(144, 2), 256>>>(w2, nullptr, b2, nullptr, 128, 256, 18432, -1, 0, 1);
    k_im2col_b<<<dim3(50, 512), 256>>>(1, 36, 6, 5, 25, 12800);
    k_bgemm<1,0,1><<<dim3(100, 4), 256>>>(w3, nullptr, b3, nullptr, 256, 512, 12800, -1, 0, 2);
    k_im2col_b<<<dim3(32, 1024), 256>>>(2, 25, 5, 4, 16, 8192);
    k_bgemm<0,0,1><<<dim3(64, 2), 256>>>(pw, nullptr, pb, nullptr, 96, 1024, 8192, -1, 0, 3);
    k_squash<<<(NI*NB + 255)/256, 256>>>();

    // capsule layer
    k_einsum<<<dim3(32, NO), 384, einsum_smem>>>(capsW);
    k_routefuse<<<NB, 512, route_smem>>>(capsB, out);

    // MLP tail
    k_fc1<<<dim3(4, 2048), 256>>>(f1w, f1b);
    k_bgemm<1,0,0><<<dim3(6, 32), 256>>>(nullptr, f2w, f2b, nullptr, 2048, 1024, 768, 4, -1, 5);
    k_bgemm<1,0,0><<<dim3(4, 32), 256>>>(nullptr, f3w, f3b, nullptr, 2048, 768,  512, 5, -1, 6);
    k_bgemm<1,0,0><<<dim3(4, 32), 256>>>(nullptr, f4w, f4b, nullptr, 2048, 512,  512, 6, -1, 7);
    k_bgemm<1,0,0><<<dim3(2, 32), 256>>>(nullptr, f5w, f5b, nullptr, 2048, 512,  256, 7, -1, 8);
    k_bgemm<0,1,0><<<dim3(1, 32), 256>>>(nullptr, hw,  hb,  out,     2048, 256,  128, 8, -1, -1);
    (void)in_sizes; (void)n_in; (void)out_size;
}